// round 13
// baseline (speedup 1.0000x reference)
#include <cuda_runtime.h>
#include <cuda_bf16.h>
#include <math.h>

#define Bb 8
#define Nb 300
#define Rr 36
#define Cc 256
#define CONF_THR 0.3f
#define IOU_THR 0.7f
#define NW 10            // ceil(Nb/32) keep-mask words

#define CG 8             // channel groups per ROI
#define CPB 32           // channels per block (Cc / CG)
#define NMS_BLOCKS 8
#define ROI_BLOCKS (CG * Bb * Rr)   // 2304
#define NT 256

// scratch (allocation-free): selected boxes + packed (level<<1 | valid)
__device__ float4 g_selbox[Bb * Rr];
__device__ int    g_selinfo[Bb * Rr];
__device__ int    g_count;   // nms-done counter (self-resetting each replay)
__device__ int    g_done;    // roi-done counter (self-resetting each replay)

struct NmsS {
    unsigned long long skey[Nb];
    float4       sb[Nb];
    float        sarea[Nb];
    unsigned int srow[Nb * NW];   // suppression bit-matrix (j>i only)
    unsigned int validw[NW];
    unsigned int keepw[NW];
};
struct RoiS {
    int4   soff[196];
    float4 swts[196];
};
union SmemU {
    NmsS n;
    RoiS r;
};

__device__ __forceinline__
void nms_part(int b, const float* __restrict__ boxes,
              const float* __restrict__ scores, NmsS& S)
{
    const int tid = threadIdx.x;

    // ---- build sort keys: descending score (thresholded), stable by index ----
    for (int i = tid; i < Nb; i += NT) {
        float s  = scores[b * Nb + i];
        float sv = (s > CONF_THR) ? s : -INFINITY;
        unsigned int bits = __float_as_uint(sv);
        unsigned int u = bits ^ ((bits >> 31) ? 0xFFFFFFFFu : 0x80000000u);
        // smaller key = higher score (lower index on tie) -> rank = sorted pos
        S.skey[i] = (((unsigned long long)(~u)) << 32) | (unsigned int)i;
    }
    if (tid < NW) S.validw[tid] = 0u;
    __syncthreads();

    // ---- rank sort: exact stable argsort(-s) ----
    for (int i = tid; i < Nb; i += NT) {
        unsigned long long mykey = S.skey[i];
        int r = 0;
        #pragma unroll 10
        for (int j = 0; j < Nb; j++) r += (S.skey[j] < mykey);
        const float* bp = boxes + ((size_t)b * Nb + i) * 4;
        float4 bx = make_float4(bp[0], bp[1], bp[2], bp[3]);
        S.sb[r]    = bx;
        S.sarea[r] = (bx.z - bx.x) * (bx.w - bx.y);
        float s = scores[b * Nb + i];
        if (s > CONF_THR) atomicOr(&S.validw[r >> 5], 1u << (r & 31));
    }
    __syncthreads();

    // ---- suppression bit matrix: bit j of word (i,w) set iff j>i & iou>THR ----
    for (int t = tid; t < Nb * NW; t += NT) {
        int i = t / NW;
        int w = t - i * NW;
        unsigned int bits = 0u;
        int j0 = w << 5;
        if (j0 + 31 > i) {
            float4 bi = S.sb[i];
            float  ai = S.sarea[i];
            int jbeg = max(j0, i + 1);
            int jend = min(j0 + 32, Nb);
            for (int j = jbeg; j < jend; j++) {
                float4 bj = S.sb[j];
                float ltx = fmaxf(bi.x, bj.x);
                float lty = fmaxf(bi.y, bj.y);
                float rbx = fminf(bi.z, bj.z);
                float rby = fminf(bi.w, bj.w);
                float ww = fmaxf(rbx - ltx, 0.0f);
                float hh = fmaxf(rby - lty, 0.0f);
                float inter = ww * hh;
                float iou = inter / (ai + S.sarea[j] - inter + 1e-9f);
                if (iou > IOU_THR) bits |= 1u << (j - j0);
            }
        }
        S.srow[t] = bits;
    }
    __syncthreads();

    // ---- greedy suppression: single warp, no barriers ----
    if (tid < 32) {
        unsigned int kw   = (tid < NW) ? S.validw[tid] : 0u;
        unsigned int nrow = (tid < NW) ? S.srow[tid]   : 0u;
        for (int i = 0; i < Nb; i++) {
            unsigned int row = nrow;
            if (tid < NW && i + 1 < Nb) nrow = S.srow[(i + 1) * NW + tid];
            unsigned int wi = __shfl_sync(0xFFFFFFFFu, kw, i >> 5);
            if ((wi >> (i & 31)) & 1u) kw &= ~row;
        }
        if (tid < NW) S.keepw[tid] = kw;
    }
    __syncthreads();

    // ---- parallel stable partition (kept first), take first Rr, FPN level ----
    for (int i = tid; i < Nb; i += NT) {
        int w   = i >> 5;
        int bit = i & 31;
        unsigned int myw = S.keepw[w];
        int kept = (myw >> bit) & 1;
        int kpre = __popc(myw & ((1u << bit) - 1u));
        for (int u = 0; u < w; u++) kpre += __popc(S.keepw[u]);
        int K = 0;
        #pragma unroll
        for (int u = 0; u < NW; u++) K += __popc(S.keepw[u]);
        int slot = kept ? kpre : (K + (i - kpre));
        if (slot < Rr) {
            float4 bx = S.sb[i];
            g_selbox[b * Rr + slot] = bx;
            float dx = bx.z - bx.x;
            float dy = bx.w - bx.y;
            float size = sqrtf(fmaxf(dx * dx + dy * dy, 1e-12f));
            float t = floorf(4.0f + log2f(size / 224.0f * 4.0f));
            t = fminf(fmaxf(t, 2.0f), 5.0f);
            int lv = (int)t - 2;
            g_selinfo[b * Rr + slot] = (lv << 1) | kept;
        }
    }

    // ---- publish: all writes device-visible, then signal ----
    __threadfence();
    __syncthreads();
    if (tid == 0) atomicAdd(&g_count, 1);
}

__device__ __forceinline__
void roi_part(int wu, const float* __restrict__ f0, const float* __restrict__ f1,
              const float* __restrict__ f2, const float* __restrict__ f3,
              float* __restrict__ out, RoiS& S)
{
    const int cg  = wu & (CG - 1);
    const int rid = wu >> 3;             // / CG
    const int b   = rid / Rr;
    const int tid = threadIdx.x;
    float* o = out + (size_t)rid * Cc + cg * CPB;

    // ---- gate on nms completion (tid 0 spins, rest park at barrier) ----
    if (tid == 0) {
        while (*(volatile int*)&g_count < NMS_BLOCKS) __nanosleep(128);
    }
    __syncthreads();
    __threadfence();    // acquire: order subsequent loads after flag observation

    const int info = g_selinfo[rid];
    if (info & 1) {
        const int lv = info >> 1;
        const float* feat;
        int H, W;
        if      (lv == 0) { feat = f0; H = 200; W = 200; }
        else if (lv == 1) { feat = f1; H = 100; W = 100; }
        else if (lv == 2) { feat = f2; H = 50;  W = 50;  }
        else              { feat = f3; H = 25;  W = 25;  }
        const int HW = H * W;
        const float* fb = feat + ((size_t)b * Cc + cg * CPB) * HW;

        const float4 bx = g_selbox[rid];
        const float rw = fmaxf(bx.z - bx.x, 1.0f);
        const float rh = fmaxf(bx.w - bx.y, 1.0f);

        if (tid < 196) {
            int gy = tid / 14;
            int gx = tid - gy * 14;
            float Y = bx.y + rh * ((gy + 0.5f) / 14.0f);
            float X = bx.x + rw * ((gx + 0.5f) / 14.0f);
            float Hf = (float)H, Wf = (float)W;
            bool oob = (Y < -1.0f) || (Y > Hf) || (X < -1.0f) || (X > Wf);
            float y = fminf(fmaxf(Y, 0.0f), Hf - 1.0f);
            float x = fminf(fmaxf(X, 0.0f), Wf - 1.0f);
            int y0 = (int)floorf(y);
            int x0 = (int)floorf(x);
            int y1i = min(y0 + 1, H - 1);
            int x1i = min(x0 + 1, W - 1);
            float ly = y - (float)y0;
            float lx = x - (float)x0;
            float w00 = (1.0f - ly) * (1.0f - lx);
            float w01 = (1.0f - ly) * lx;
            float w10 = ly * (1.0f - lx);
            float w11 = ly * lx;
            if (oob) {
                w00 = w01 = w10 = w11 = 0.0f;
                S.soff[tid] = make_int4(0, 0, 0, 0);
            } else {
                S.soff[tid] = make_int4(y0 * W + x0, y0 * W + x1i, y1i * W + x0, y1i * W + x1i);
            }
            S.swts[tid] = make_float4(w00, w01, w10, w11);
        }
        __syncthreads();

        const int warp = tid >> 5;
        const int lane = tid & 31;
        const int c0 = warp * 4;
        const float* fB = fb + (size_t)c0 * HW;

        float acc[4] = {0.0f, 0.0f, 0.0f, 0.0f};

        #pragma unroll
        for (int k = 0; k < 7; k++) {
            int p  = lane + 32 * k;
            int sp = (p < 196) ? p : 0;
            int4   oo = S.soff[sp];
            float4 ww = S.swts[sp];
            if (p >= 196) ww = make_float4(0.0f, 0.0f, 0.0f, 0.0f);
            float v[4][4];
            #pragma unroll
            for (int c = 0; c < 4; c++) {
                const float* f = fB + c * HW;
                v[c][0] = f[oo.x];
                v[c][1] = f[oo.y];
                v[c][2] = f[oo.z];
                v[c][3] = f[oo.w];
            }
            #pragma unroll
            for (int c = 0; c < 4; c++) {
                acc[c] += v[c][0] * ww.x + v[c][1] * ww.y + v[c][2] * ww.z + v[c][3] * ww.w;
            }
        }

        #pragma unroll
        for (int s = 16; s; s >>= 1) {
            acc[0] += __shfl_down_sync(0xFFFFFFFFu, acc[0], s);
            acc[1] += __shfl_down_sync(0xFFFFFFFFu, acc[1], s);
            acc[2] += __shfl_down_sync(0xFFFFFFFFu, acc[2], s);
            acc[3] += __shfl_down_sync(0xFFFFFFFFu, acc[3], s);
        }
        if (lane == 0) {
            o[c0 + 0] = acc[0] * (1.0f / 196.0f);
            o[c0 + 1] = acc[1] * (1.0f / 196.0f);
            o[c0 + 2] = acc[2] * (1.0f / 196.0f);
            o[c0 + 3] = acc[3] * (1.0f / 196.0f);
        }
    } else {
        if (tid < CPB) o[tid] = 0.0f;    // invalid ROI -> zeros
    }

    // ---- epoch reset: last roi block to finish rearms counters for next replay ----
    __syncthreads();
    if (tid == 0) {
        int old = atomicAdd(&g_done, 1);
        if (old == ROI_BLOCKS - 1) {
            g_count = 0;
            g_done  = 0;
            // kernel-exit implicit fence orders these before the next replay
        }
    }
}

__global__ __launch_bounds__(NT)
void fused_kernel(const float* __restrict__ boxes, const float* __restrict__ scores,
                  const float* __restrict__ f0, const float* __restrict__ f1,
                  const float* __restrict__ f2, const float* __restrict__ f3,
                  float* __restrict__ out)
{
    __shared__ SmemU S;
    const int bid = blockIdx.x;
    if (bid < NMS_BLOCKS) {
        nms_part(bid, boxes, scores, S.n);
    } else {
        roi_part(bid - NMS_BLOCKS, f0, f1, f2, f3, out, S.r);
    }
}

extern "C" void kernel_launch(void* const* d_in, const int* in_sizes, int n_in,
                              void* d_out, int out_size)
{
    const float* boxes  = (const float*)d_in[0]; // (B,N,4)
    const float* scores = (const float*)d_in[1]; // (B,N)
    const float* f0     = (const float*)d_in[2]; // (B,C,200,200)
    const float* f1     = (const float*)d_in[3]; // (B,C,100,100)
    const float* f2     = (const float*)d_in[4]; // (B,C,50,50)
    const float* f3     = (const float*)d_in[5]; // (B,C,25,25)
    float* out          = (float*)d_out;         // (B,R,C)

    fused_kernel<<<NMS_BLOCKS + ROI_BLOCKS, NT>>>(boxes, scores, f0, f1, f2, f3, out);
}